// round 9
// baseline (speedup 1.0000x reference)
#include <cuda_runtime.h>
#include <cstdint>

// LIF scan over time axis. x: [rows, T=100] fp32, T contiguous.
// mem = prev_sp ? x : (mem*DECAY + x);  sp = mem > THRESH  (rounding-identical
// to reference's mem*DECAY*(1-sp)+x since sp is exactly 0 or 1).
//
// R9: R4 fine-grain pipeline (64-row chunks, 2 CTAs/SM capacity, in-place
// 4-deep bulk-TMA ring, hoisted load issue) launched at grid=256:
//  - 8192 chunks / 256 CTAs = 32 each -> perfect static balance
//  - 256 < 304 resident-capacity -> all CTAs co-resident even on a dirty
//    chip, so no straggler wave (this was R7's bench win, generalized).

#define LIF_THRESH 0.5f
#define LIF_DECAY  0.2f
#define LIF_T      100
#define LIF_TV     25                          // float4 per row (odd stride -> conflict-free)
#define CHUNK_ROWS 64
#define THREADS    64
#define NBUF       4
#define CHUNK_BYTES (CHUNK_ROWS * LIF_T * 4)   // 25600
#define SM_IN       1024                        // after mbarriers
#define SM_TOTAL    (SM_IN + NBUF * CHUNK_BYTES)  // 103424 bytes -> 2 CTAs/SM

__device__ __forceinline__ uint32_t smem_u32(const void* p) {
    uint32_t a;
    asm("{ .reg .u64 t; cvta.to.shared.u64 t, %1; cvt.u32.u64 %0, t; }" : "=r"(a) : "l"(p));
    return a;
}
__device__ __forceinline__ void mbar_init(uint32_t mbar, uint32_t cnt) {
    asm volatile("mbarrier.init.shared.b64 [%0], %1;" :: "r"(mbar), "r"(cnt) : "memory");
}
__device__ __forceinline__ void mbar_expect(uint32_t mbar, uint32_t bytes) {
    asm volatile("mbarrier.arrive.expect_tx.shared.b64 _, [%0], %1;" :: "r"(mbar), "r"(bytes) : "memory");
}
__device__ __forceinline__ void mbar_wait(uint32_t mbar, uint32_t parity) {
    uint32_t done;
    asm volatile(
        "{\n\t.reg .pred p;\n\t"
        "mbarrier.try_wait.parity.acquire.cta.shared::cta.b64 p, [%1], %2;\n\t"
        "selp.b32 %0, 1, 0, p;\n\t}"
        : "=r"(done) : "r"(mbar), "r"(parity) : "memory");
    if (!done) {
        asm volatile(
            "{\n\t.reg .pred P1;\n\t"
            "W_%=:\n\t"
            "mbarrier.try_wait.parity.acquire.cta.shared::cta.b64 P1, [%0], %1, 0x989680;\n\t"
            "@P1 bra.uni D_%=;\n\t"
            "bra.uni W_%=;\n\t"
            "D_%=:\n\t}"
            :: "r"(mbar), "r"(parity) : "memory");
    }
}
__device__ __forceinline__ void bulk_g2s(uint32_t dst_smem, const void* src, uint32_t bytes, uint32_t mbar) {
    asm volatile(
        "cp.async.bulk.shared::cluster.global.mbarrier::complete_tx::bytes [%0], [%1], %2, [%3];"
        :: "r"(dst_smem), "l"(src), "r"(bytes), "r"(mbar) : "memory");
}
__device__ __forceinline__ void bulk_s2g(void* dst, uint32_t src_smem, uint32_t bytes) {
    asm volatile(
        "cp.async.bulk.global.shared::cta.bulk_group [%0], [%1], %2;"
        :: "l"(dst), "r"(src_smem), "r"(bytes) : "memory");
}

__global__ __launch_bounds__(THREADS, 2)
void lif_tma_kernel(const char* __restrict__ gin, char* __restrict__ gout,
                    int n_chunks) {
    extern __shared__ char smem[];
    const uint32_t sbase = smem_u32(smem);
    const int tid = threadIdx.x;
    const int stride = gridDim.x;

    if ((int)blockIdx.x >= n_chunks) return;
    // Block-strided chunks: local l -> global chunk blockIdx.x + l*stride.
    const int ncl = (n_chunks - (int)blockIdx.x + stride - 1) / stride;

    if (tid == 0) {
        #pragma unroll
        for (int b = 0; b < NBUF; b++) mbar_init(sbase + 8 * b, 1);
        asm volatile("fence.proxy.async.shared::cta;" ::: "memory");
    }
    __syncthreads();

    // Prologue: prefetch up to 3 chunks.
    if (tid == 0) {
        int pre = ncl < 3 ? ncl : 3;
        for (int l = 0; l < pre; l++) {
            long long g = (long long)blockIdx.x + (long long)l * stride;
            mbar_expect(sbase + 8 * l, CHUNK_BYTES);
            bulk_g2s(sbase + SM_IN + l * CHUNK_BYTES,
                     gin + g * CHUNK_BYTES, CHUNK_BYTES, sbase + 8 * l);
        }
    }

    for (int l = 0; l < ncl; l++) {
        const int b = l & (NBUF - 1);
        const long long g = (long long)blockIdx.x + (long long)l * stride;

        // Keep the load pipeline full BEFORE scanning: buffer (l+3)&3 held
        // chunk l-1, whose store was committed at the end of iter l-1;
        // wait_group.read 0 guarantees its smem has been fully read out.
        if (tid == 0 && l + 3 < ncl) {
            asm volatile("cp.async.bulk.wait_group.read 0;" ::: "memory");
            const int nb = (l + 3) & (NBUF - 1);
            const long long ng = (long long)blockIdx.x + (long long)(l + 3) * stride;
            mbar_expect(sbase + 8 * nb, CHUNK_BYTES);
            bulk_g2s(sbase + SM_IN + nb * CHUNK_BYTES,
                     gin + ng * CHUNK_BYTES, CHUNK_BYTES, sbase + 8 * nb);
        }

        // Wait for load of chunk l (buffer b, 4-use parity).
        mbar_wait(sbase + 8 * b, (l >> 2) & 1);

        // Streaming in-place scan: read f4, compute, write spikes back.
        float4* row = (float4*)(smem + SM_IN + b * CHUNK_BYTES) + tid * LIF_TV;
        float mem = 0.0f;
        bool sp = false;
        #pragma unroll
        for (int k = 0; k < LIF_TV; k++) {
            float4 v = row[k];
            float4 o;
            float t;
            t = __fadd_rn(__fmul_rn(mem, LIF_DECAY), v.x);
            mem = sp ? v.x : t;  sp = mem > LIF_THRESH;  o.x = sp ? 1.0f : 0.0f;
            t = __fadd_rn(__fmul_rn(mem, LIF_DECAY), v.y);
            mem = sp ? v.y : t;  sp = mem > LIF_THRESH;  o.y = sp ? 1.0f : 0.0f;
            t = __fadd_rn(__fmul_rn(mem, LIF_DECAY), v.z);
            mem = sp ? v.z : t;  sp = mem > LIF_THRESH;  o.z = sp ? 1.0f : 0.0f;
            t = __fadd_rn(__fmul_rn(mem, LIF_DECAY), v.w);
            mem = sp ? v.w : t;  sp = mem > LIF_THRESH;  o.w = sp ? 1.0f : 0.0f;
            row[k] = o;
        }

        // Publish STS to the async proxy, then store chunk l.
        asm volatile("fence.proxy.async.shared::cta;" ::: "memory");
        __syncthreads();
        if (tid == 0) {
            bulk_s2g(gout + g * CHUNK_BYTES,
                     sbase + SM_IN + b * CHUNK_BYTES, CHUNK_BYTES);
            asm volatile("cp.async.bulk.commit_group;" ::: "memory");
        }
    }

    // Keep smem alive until all pending bulk stores have read it.
    if (tid == 0)
        asm volatile("cp.async.bulk.wait_group.read 0;" ::: "memory");
}

// Scalar tail for rows not covered by full chunks.
__global__ void lif_scan_tail_kernel(const float* __restrict__ x,
                                     float* __restrict__ out,
                                     long long row_start, long long n_rows) {
    long long r = row_start + blockIdx.x * (long long)blockDim.x + threadIdx.x;
    if (r >= n_rows) return;
    const float* xr = x + r * LIF_T;
    float* orow = out + r * LIF_T;
    float mem = 0.0f;
    bool sp = false;
    #pragma unroll 4
    for (int t = 0; t < LIF_T; t++) {
        float tt = __fadd_rn(__fmul_rn(mem, LIF_DECAY), xr[t]);
        mem = sp ? xr[t] : tt;
        sp = mem > LIF_THRESH;
        orow[t] = sp ? 1.0f : 0.0f;
    }
}

extern "C" void kernel_launch(void* const* d_in, const int* in_sizes, int n_in,
                              void* d_out, int out_size) {
    const float* x = (const float*)d_in[0];
    float* out = (float*)d_out;

    long long total = (long long)in_sizes[0];
    long long n_rows = total / LIF_T;                 // 524288
    long long n_chunks = n_rows / CHUNK_ROWS;         // 8192

    if (n_chunks > 0) {
        static int smem_set = 0;
        if (!smem_set) {
            cudaFuncSetAttribute(lif_tma_kernel,
                                 cudaFuncAttributeMaxDynamicSharedMemorySize, SM_TOTAL);
            smem_set = 1;
        }
        // 256 CTAs: perfectly balanced (8192/256 = 32 chunks each) AND below
        // the 304-CTA residency capacity (2/SM x 152), so all CTAs are
        // co-resident regardless of scheduling dirt -> no straggler wave.
        long long grid = 256;
        if (n_chunks < grid) grid = n_chunks;
        lif_tma_kernel<<<(unsigned)grid, THREADS, SM_TOTAL>>>(
            (const char*)x, (char*)out, (int)n_chunks);
    }

    long long done_rows = n_chunks * CHUNK_ROWS;
    long long rem = n_rows - done_rows;
    if (rem > 0) {
        int threads = 128;
        int blocks = (int)((rem + threads - 1) / threads);
        lif_scan_tail_kernel<<<blocks, threads>>>(x, out, done_rows, n_rows);
    }
}

// round 10
// speedup vs baseline: 1.0127x; 1.0127x over previous
#include <cuda_runtime.h>
#include <cstdint>

// LIF scan over time axis. x: [rows, T=100] fp32, T contiguous.
// mem = prev_sp ? x : (mem*DECAY + x);  sp = mem > THRESH  (rounding-identical
// to reference's mem*DECAY*(1-sp)+x since sp is exactly 0 or 1).
//
// R10: fastest kernel family (grid=152, 128-row chunks, 205KB in-place 4-deep
// bulk-TMA ring, hoisted load issue) + a 1-thread SPACER kernel ahead of it
// in the captured graph. R8 showed the spacer collapses the bench-over-ncu
// gap from ~10-16us to ~2us (clean wave formation at replay boundaries).

#define LIF_THRESH 0.5f
#define LIF_DECAY  0.2f
#define LIF_T      100
#define LIF_TV     25                          // float4 per row (odd stride -> conflict-free)
#define CHUNK_ROWS 128
#define THREADS    128
#define NBUF       4
#define CHUNK_BYTES (CHUNK_ROWS * LIF_T * 4)   // 51200
#define SM_IN       1024                        // after mbarriers
#define SM_TOTAL    (SM_IN + NBUF * CHUNK_BYTES)  // 205824 bytes -> 1 CTA/SM

__device__ int g_spacer_sink;

// Graph spacer: a full-completion settle point before the wide launch.
__global__ void lif_spacer_kernel() { g_spacer_sink = 0; }

__device__ __forceinline__ uint32_t smem_u32(const void* p) {
    uint32_t a;
    asm("{ .reg .u64 t; cvta.to.shared.u64 t, %1; cvt.u32.u64 %0, t; }" : "=r"(a) : "l"(p));
    return a;
}
__device__ __forceinline__ void mbar_init(uint32_t mbar, uint32_t cnt) {
    asm volatile("mbarrier.init.shared.b64 [%0], %1;" :: "r"(mbar), "r"(cnt) : "memory");
}
__device__ __forceinline__ void mbar_expect(uint32_t mbar, uint32_t bytes) {
    asm volatile("mbarrier.arrive.expect_tx.shared.b64 _, [%0], %1;" :: "r"(mbar), "r"(bytes) : "memory");
}
__device__ __forceinline__ void mbar_wait(uint32_t mbar, uint32_t parity) {
    uint32_t done;
    asm volatile(
        "{\n\t.reg .pred p;\n\t"
        "mbarrier.try_wait.parity.acquire.cta.shared::cta.b64 p, [%1], %2;\n\t"
        "selp.b32 %0, 1, 0, p;\n\t}"
        : "=r"(done) : "r"(mbar), "r"(parity) : "memory");
    if (!done) {
        asm volatile(
            "{\n\t.reg .pred P1;\n\t"
            "W_%=:\n\t"
            "mbarrier.try_wait.parity.acquire.cta.shared::cta.b64 P1, [%0], %1, 0x989680;\n\t"
            "@P1 bra.uni D_%=;\n\t"
            "bra.uni W_%=;\n\t"
            "D_%=:\n\t}"
            :: "r"(mbar), "r"(parity) : "memory");
    }
}
__device__ __forceinline__ void bulk_g2s(uint32_t dst_smem, const void* src, uint32_t bytes, uint32_t mbar) {
    asm volatile(
        "cp.async.bulk.shared::cluster.global.mbarrier::complete_tx::bytes [%0], [%1], %2, [%3];"
        :: "r"(dst_smem), "l"(src), "r"(bytes), "r"(mbar) : "memory");
}
__device__ __forceinline__ void bulk_s2g(void* dst, uint32_t src_smem, uint32_t bytes) {
    asm volatile(
        "cp.async.bulk.global.shared::cta.bulk_group [%0], [%1], %2;"
        :: "l"(dst), "r"(src_smem), "r"(bytes) : "memory");
}

__global__ __launch_bounds__(THREADS, 1)
void lif_tma_kernel(const char* __restrict__ gin, char* __restrict__ gout,
                    int n_chunks) {
    extern __shared__ char smem[];
    const uint32_t sbase = smem_u32(smem);
    const int tid = threadIdx.x;
    const int stride = gridDim.x;

    if ((int)blockIdx.x >= n_chunks) return;
    // Block-strided chunks: local l -> global chunk blockIdx.x + l*stride.
    const int ncl = (n_chunks - (int)blockIdx.x + stride - 1) / stride;

    if (tid == 0) {
        #pragma unroll
        for (int b = 0; b < NBUF; b++) mbar_init(sbase + 8 * b, 1);
        asm volatile("fence.proxy.async.shared::cta;" ::: "memory");
    }
    __syncthreads();

    // Prologue: prefetch up to 3 chunks.
    if (tid == 0) {
        int pre = ncl < 3 ? ncl : 3;
        for (int l = 0; l < pre; l++) {
            long long g = (long long)blockIdx.x + (long long)l * stride;
            mbar_expect(sbase + 8 * l, CHUNK_BYTES);
            bulk_g2s(sbase + SM_IN + l * CHUNK_BYTES,
                     gin + g * CHUNK_BYTES, CHUNK_BYTES, sbase + 8 * l);
        }
    }

    for (int l = 0; l < ncl; l++) {
        const int b = l & (NBUF - 1);
        const long long g = (long long)blockIdx.x + (long long)l * stride;

        // Keep the load pipeline full BEFORE scanning: buffer (l+3)&3 held
        // chunk l-1, whose store was committed at the end of iter l-1;
        // wait_group.read 0 guarantees its smem has been fully read out.
        if (tid == 0 && l + 3 < ncl) {
            asm volatile("cp.async.bulk.wait_group.read 0;" ::: "memory");
            const int nb = (l + 3) & (NBUF - 1);
            const long long ng = (long long)blockIdx.x + (long long)(l + 3) * stride;
            mbar_expect(sbase + 8 * nb, CHUNK_BYTES);
            bulk_g2s(sbase + SM_IN + nb * CHUNK_BYTES,
                     gin + ng * CHUNK_BYTES, CHUNK_BYTES, sbase + 8 * nb);
        }

        // Wait for load of chunk l (buffer b, 4-use parity).
        mbar_wait(sbase + 8 * b, (l >> 2) & 1);

        // Streaming in-place scan: read f4, compute, write spikes back.
        float4* row = (float4*)(smem + SM_IN + b * CHUNK_BYTES) + tid * LIF_TV;
        float mem = 0.0f;
        bool sp = false;
        #pragma unroll
        for (int k = 0; k < LIF_TV; k++) {
            float4 v = row[k];
            float4 o;
            float t;
            t = __fadd_rn(__fmul_rn(mem, LIF_DECAY), v.x);
            mem = sp ? v.x : t;  sp = mem > LIF_THRESH;  o.x = sp ? 1.0f : 0.0f;
            t = __fadd_rn(__fmul_rn(mem, LIF_DECAY), v.y);
            mem = sp ? v.y : t;  sp = mem > LIF_THRESH;  o.y = sp ? 1.0f : 0.0f;
            t = __fadd_rn(__fmul_rn(mem, LIF_DECAY), v.z);
            mem = sp ? v.z : t;  sp = mem > LIF_THRESH;  o.z = sp ? 1.0f : 0.0f;
            t = __fadd_rn(__fmul_rn(mem, LIF_DECAY), v.w);
            mem = sp ? v.w : t;  sp = mem > LIF_THRESH;  o.w = sp ? 1.0f : 0.0f;
            row[k] = o;
        }

        // Publish STS to the async proxy, then store chunk l.
        asm volatile("fence.proxy.async.shared::cta;" ::: "memory");
        __syncthreads();
        if (tid == 0) {
            bulk_s2g(gout + g * CHUNK_BYTES,
                     sbase + SM_IN + b * CHUNK_BYTES, CHUNK_BYTES);
            asm volatile("cp.async.bulk.commit_group;" ::: "memory");
        }
    }

    // Keep smem alive until all pending bulk stores have read it.
    if (tid == 0)
        asm volatile("cp.async.bulk.wait_group.read 0;" ::: "memory");
}

// Scalar tail for rows not covered by full chunks.
__global__ void lif_scan_tail_kernel(const float* __restrict__ x,
                                     float* __restrict__ out,
                                     long long row_start, long long n_rows) {
    long long r = row_start + blockIdx.x * (long long)blockDim.x + threadIdx.x;
    if (r >= n_rows) return;
    const float* xr = x + r * LIF_T;
    float* orow = out + r * LIF_T;
    float mem = 0.0f;
    bool sp = false;
    #pragma unroll 4
    for (int t = 0; t < LIF_T; t++) {
        float tt = __fadd_rn(__fmul_rn(mem, LIF_DECAY), xr[t]);
        mem = sp ? xr[t] : tt;
        sp = mem > LIF_THRESH;
        orow[t] = sp ? 1.0f : 0.0f;
    }
}

extern "C" void kernel_launch(void* const* d_in, const int* in_sizes, int n_in,
                              void* d_out, int out_size) {
    const float* x = (const float*)d_in[0];
    float* out = (float*)d_out;

    long long total = (long long)in_sizes[0];
    long long n_rows = total / LIF_T;                 // 524288
    long long n_chunks = n_rows / CHUNK_ROWS;         // 4096

    if (n_chunks > 0) {
        static int smem_set = 0;
        if (!smem_set) {
            cudaFuncSetAttribute(lif_tma_kernel,
                                 cudaFuncAttributeMaxDynamicSharedMemorySize, SM_TOTAL);
            smem_set = 1;
        }
        // Spacer node: full-completion settle point before the wide launch.
        lif_spacer_kernel<<<1, 1>>>();
        // One CTA per SM (GB300: 152 SMs), block-strided work (27/26 chunks,
        // imbalance cost ~0.2us).
        long long grid = 152;
        if (n_chunks < grid) grid = n_chunks;
        lif_tma_kernel<<<(unsigned)grid, THREADS, SM_TOTAL>>>(
            (const char*)x, (char*)out, (int)n_chunks);
    }

    long long done_rows = n_chunks * CHUNK_ROWS;
    long long rem = n_rows - done_rows;
    if (rem > 0) {
        int threads = 128;
        int blocks = (int)((rem + threads - 1) / threads);
        lif_scan_tail_kernel<<<blocks, threads>>>(x, out, done_rows, n_rows);
    }
}

// round 11
// speedup vs baseline: 1.1317x; 1.1174x over previous
#include <cuda_runtime.h>
#include <cstdint>

// LIF scan over time axis. x: [rows, T=100] fp32, T contiguous.
// mem = prev_sp ? x : (mem*DECAY + x);  sp = mem > THRESH  (rounding-identical
// to reference's mem*DECAY*(1-sp)+x since sp is exactly 0 or 1).
//
// R11: bulk-TMA in-place 4-deep ring + PIPELINED work-stealing. Dynamic
// stealing absorbs replay-boundary stagger (R8 evidence: gap 16us -> 2us);
// the atomicAdd is pre-stolen one iteration ahead so its ~320cyc latency
// hides under the scan instead of delaying load issue (R8's regression).

#define LIF_THRESH 0.5f
#define LIF_DECAY  0.2f
#define LIF_T      100
#define LIF_TV     25                          // float4 per row (odd stride -> conflict-free)
#define CHUNK_ROWS 128
#define THREADS    128
#define NBUF       4
#define CHUNK_BYTES (CHUNK_ROWS * LIF_T * 4)   // 51200
#define SM_ID       64                          // s_id[4] ints at byte 64
#define SM_IN       1024                        // buffers after mbars/ids
#define SM_TOTAL    (SM_IN + NBUF * CHUNK_BYTES)  // 205824 bytes -> 1 CTA/SM

__device__ unsigned int g_next_chunk;

__global__ void lif_reset_kernel() { g_next_chunk = 0u; }

__device__ __forceinline__ uint32_t smem_u32(const void* p) {
    uint32_t a;
    asm("{ .reg .u64 t; cvta.to.shared.u64 t, %1; cvt.u32.u64 %0, t; }" : "=r"(a) : "l"(p));
    return a;
}
__device__ __forceinline__ void mbar_init(uint32_t mbar, uint32_t cnt) {
    asm volatile("mbarrier.init.shared.b64 [%0], %1;" :: "r"(mbar), "r"(cnt) : "memory");
}
__device__ __forceinline__ void mbar_expect(uint32_t mbar, uint32_t bytes) {
    asm volatile("mbarrier.arrive.expect_tx.shared.b64 _, [%0], %1;" :: "r"(mbar), "r"(bytes) : "memory");
}
__device__ __forceinline__ void mbar_wait(uint32_t mbar, uint32_t parity) {
    uint32_t done;
    asm volatile(
        "{\n\t.reg .pred p;\n\t"
        "mbarrier.try_wait.parity.acquire.cta.shared::cta.b64 p, [%1], %2;\n\t"
        "selp.b32 %0, 1, 0, p;\n\t}"
        : "=r"(done) : "r"(mbar), "r"(parity) : "memory");
    if (!done) {
        asm volatile(
            "{\n\t.reg .pred P1;\n\t"
            "W_%=:\n\t"
            "mbarrier.try_wait.parity.acquire.cta.shared::cta.b64 P1, [%0], %1, 0x989680;\n\t"
            "@P1 bra.uni D_%=;\n\t"
            "bra.uni W_%=;\n\t"
            "D_%=:\n\t}"
            :: "r"(mbar), "r"(parity) : "memory");
    }
}
__device__ __forceinline__ void bulk_g2s(uint32_t dst_smem, const void* src, uint32_t bytes, uint32_t mbar) {
    asm volatile(
        "cp.async.bulk.shared::cluster.global.mbarrier::complete_tx::bytes [%0], [%1], %2, [%3];"
        :: "r"(dst_smem), "l"(src), "r"(bytes), "r"(mbar) : "memory");
}
__device__ __forceinline__ void bulk_s2g(void* dst, uint32_t src_smem, uint32_t bytes) {
    asm volatile(
        "cp.async.bulk.global.shared::cta.bulk_group [%0], [%1], %2;"
        :: "l"(dst), "r"(src_smem), "r"(bytes) : "memory");
}

__global__ __launch_bounds__(THREADS, 1)
void lif_tma_kernel(const char* __restrict__ gin, char* __restrict__ gout,
                    unsigned int n_chunks) {
    extern __shared__ char smem[];
    const uint32_t sbase = smem_u32(smem);
    const int tid = threadIdx.x;
    int* s_id = (int*)(smem + SM_ID);   // chunk id held by each ring slot (-1 = none)

    int next_id = -1;                   // tid 0 only: pre-stolen chunk for next refill

    if (tid == 0) {
        #pragma unroll
        for (int b = 0; b < NBUF; b++) mbar_init(sbase + 8 * b, 1);
        asm volatile("fence.proxy.async.shared::cta;" ::: "memory");
        // Prologue: steal 3 chunks, start their loads, pre-steal one more.
        for (int l = 0; l < 3; l++) {
            unsigned int id = atomicAdd(&g_next_chunk, 1u);
            int v = (id < n_chunks) ? (int)id : -1;
            s_id[l] = v;
            if (v >= 0) {
                mbar_expect(sbase + 8 * l, CHUNK_BYTES);
                bulk_g2s(sbase + SM_IN + l * CHUNK_BYTES,
                         gin + (long long)v * CHUNK_BYTES, CHUNK_BYTES, sbase + 8 * l);
            }
        }
        unsigned int id = atomicAdd(&g_next_chunk, 1u);
        next_id = (id < n_chunks) ? (int)id : -1;
    }
    __syncthreads();

    for (int l = 0; ; l++) {
        const int b = l & (NBUF - 1);
        const int gid = s_id[b];         // written >=1 barrier ago; CTA-uniform
        if (gid < 0) break;

        // Refill slot (l+3)&3 IMMEDIATELY with the pre-stolen id (no atomic
        // on this path), then steal the next id; its latency hides under the
        // mbar_wait + scan below.
        if (tid == 0) {
            asm volatile("cp.async.bulk.wait_group.read 0;" ::: "memory");
            const int nb = (l + 3) & (NBUF - 1);
            s_id[nb] = next_id;
            if (next_id >= 0) {
                mbar_expect(sbase + 8 * nb, CHUNK_BYTES);
                bulk_g2s(sbase + SM_IN + nb * CHUNK_BYTES,
                         gin + (long long)next_id * CHUNK_BYTES, CHUNK_BYTES,
                         sbase + 8 * nb);
            }
            unsigned int id = atomicAdd(&g_next_chunk, 1u);
            next_id = (id < n_chunks) ? (int)id : -1;
        }

        // Wait for this slot's load (4-use parity).
        mbar_wait(sbase + 8 * b, (l >> 2) & 1);

        // Streaming in-place scan: read f4, compute, write spikes back.
        float4* row = (float4*)(smem + SM_IN + b * CHUNK_BYTES) + tid * LIF_TV;
        float mem = 0.0f;
        bool sp = false;
        #pragma unroll
        for (int k = 0; k < LIF_TV; k++) {
            float4 v = row[k];
            float4 o;
            float t;
            t = __fadd_rn(__fmul_rn(mem, LIF_DECAY), v.x);
            mem = sp ? v.x : t;  sp = mem > LIF_THRESH;  o.x = sp ? 1.0f : 0.0f;
            t = __fadd_rn(__fmul_rn(mem, LIF_DECAY), v.y);
            mem = sp ? v.y : t;  sp = mem > LIF_THRESH;  o.y = sp ? 1.0f : 0.0f;
            t = __fadd_rn(__fmul_rn(mem, LIF_DECAY), v.z);
            mem = sp ? v.z : t;  sp = mem > LIF_THRESH;  o.z = sp ? 1.0f : 0.0f;
            t = __fadd_rn(__fmul_rn(mem, LIF_DECAY), v.w);
            mem = sp ? v.w : t;  sp = mem > LIF_THRESH;  o.w = sp ? 1.0f : 0.0f;
            row[k] = o;
        }

        // Publish STS to the async proxy, then store this chunk.
        asm volatile("fence.proxy.async.shared::cta;" ::: "memory");
        __syncthreads();
        if (tid == 0) {
            bulk_s2g(gout + (long long)gid * CHUNK_BYTES,
                     sbase + SM_IN + b * CHUNK_BYTES, CHUNK_BYTES);
            asm volatile("cp.async.bulk.commit_group;" ::: "memory");
        }
    }

    // Keep smem alive until all pending bulk stores have read it.
    if (tid == 0)
        asm volatile("cp.async.bulk.wait_group.read 0;" ::: "memory");
}

// Scalar tail for rows not covered by full chunks.
__global__ void lif_scan_tail_kernel(const float* __restrict__ x,
                                     float* __restrict__ out,
                                     long long row_start, long long n_rows) {
    long long r = row_start + blockIdx.x * (long long)blockDim.x + threadIdx.x;
    if (r >= n_rows) return;
    const float* xr = x + r * LIF_T;
    float* orow = out + r * LIF_T;
    float mem = 0.0f;
    bool sp = false;
    #pragma unroll 4
    for (int t = 0; t < LIF_T; t++) {
        float tt = __fadd_rn(__fmul_rn(mem, LIF_DECAY), xr[t]);
        mem = sp ? xr[t] : tt;
        sp = mem > LIF_THRESH;
        orow[t] = sp ? 1.0f : 0.0f;
    }
}

extern "C" void kernel_launch(void* const* d_in, const int* in_sizes, int n_in,
                              void* d_out, int out_size) {
    const float* x = (const float*)d_in[0];
    float* out = (float*)d_out;

    long long total = (long long)in_sizes[0];
    long long n_rows = total / LIF_T;                 // 524288
    long long n_chunks = n_rows / CHUNK_ROWS;         // 4096

    if (n_chunks > 0) {
        static int smem_set = 0;
        if (!smem_set) {
            cudaFuncSetAttribute(lif_tma_kernel,
                                 cudaFuncAttributeMaxDynamicSharedMemorySize, SM_TOTAL);
            smem_set = 1;
        }
        // Reset the stealing counter (captured into the graph -> every
        // replay re-runs it; chunk->CTA mapping may vary but chunks are
        // disjoint, so output is bit-identical).
        lif_reset_kernel<<<1, 1>>>();
        long long grid = 152;
        if (n_chunks < grid) grid = n_chunks;
        lif_tma_kernel<<<(unsigned)grid, THREADS, SM_TOTAL>>>(
            (const char*)x, (char*)out, (unsigned int)n_chunks);
    }

    long long done_rows = n_chunks * CHUNK_ROWS;
    long long rem = n_rows - done_rows;
    if (rem > 0) {
        int threads = 128;
        int blocks = (int)((rem + threads - 1) / threads);
        lif_scan_tail_kernel<<<blocks, threads>>>(x, out, done_rows, n_rows);
    }
}

// round 12
// speedup vs baseline: 1.1912x; 1.0526x over previous
#include <cuda_runtime.h>
#include <cstdint>

// LIF scan over time axis. x: [rows, T=100] fp32, T contiguous.
// mem = prev_sp ? x : (mem*DECAY + x);  sp = mem > THRESH  (rounding-identical
// to reference's mem*DECAY*(1-sp)+x since sp is exactly 0 or 1).
//
// R12: best proven config (static grid=128, 128-row chunks, in-place 4-deep
// bulk-TMA ring, hoisted load issue) + L2::evict_first cache policy on both
// bulk loads and bulk stores. Input/output are stream-once: evict_first stops
// 419 MB/replay of dead lines from churning the 126 MB L2, raising sustained
// steady-state bandwidth (the bench-time limiter; ncu's isolated/flushed run
// defers ~126 MB of writeback past kernel end and under-reports this).

#define LIF_THRESH 0.5f
#define LIF_DECAY  0.2f
#define LIF_T      100
#define LIF_TV     25                          // float4 per row (odd stride -> conflict-free)
#define CHUNK_ROWS 128
#define THREADS    128
#define NBUF       4
#define CHUNK_BYTES (CHUNK_ROWS * LIF_T * 4)   // 51200
#define SM_IN       1024                        // after mbarriers
#define SM_TOTAL    (SM_IN + NBUF * CHUNK_BYTES)  // 205824 bytes -> 1 CTA/SM

__device__ __forceinline__ uint32_t smem_u32(const void* p) {
    uint32_t a;
    asm("{ .reg .u64 t; cvta.to.shared.u64 t, %1; cvt.u32.u64 %0, t; }" : "=r"(a) : "l"(p));
    return a;
}
__device__ __forceinline__ uint64_t make_evict_first_policy() {
    uint64_t pol;
    asm("createpolicy.fractional.L2::evict_first.b64 %0, 1.0;" : "=l"(pol));
    return pol;
}
__device__ __forceinline__ void mbar_init(uint32_t mbar, uint32_t cnt) {
    asm volatile("mbarrier.init.shared.b64 [%0], %1;" :: "r"(mbar), "r"(cnt) : "memory");
}
__device__ __forceinline__ void mbar_expect(uint32_t mbar, uint32_t bytes) {
    asm volatile("mbarrier.arrive.expect_tx.shared.b64 _, [%0], %1;" :: "r"(mbar), "r"(bytes) : "memory");
}
__device__ __forceinline__ void mbar_wait(uint32_t mbar, uint32_t parity) {
    uint32_t done;
    asm volatile(
        "{\n\t.reg .pred p;\n\t"
        "mbarrier.try_wait.parity.acquire.cta.shared::cta.b64 p, [%1], %2;\n\t"
        "selp.b32 %0, 1, 0, p;\n\t}"
        : "=r"(done) : "r"(mbar), "r"(parity) : "memory");
    if (!done) {
        asm volatile(
            "{\n\t.reg .pred P1;\n\t"
            "W_%=:\n\t"
            "mbarrier.try_wait.parity.acquire.cta.shared::cta.b64 P1, [%0], %1, 0x989680;\n\t"
            "@P1 bra.uni D_%=;\n\t"
            "bra.uni W_%=;\n\t"
            "D_%=:\n\t}"
            :: "r"(mbar), "r"(parity) : "memory");
    }
}
__device__ __forceinline__ void bulk_g2s(uint32_t dst_smem, const void* src, uint32_t bytes,
                                         uint32_t mbar, uint64_t pol) {
    asm volatile(
        "cp.async.bulk.shared::cluster.global.mbarrier::complete_tx::bytes.L2::cache_hint"
        " [%0], [%1], %2, [%3], %4;"
        :: "r"(dst_smem), "l"(src), "r"(bytes), "r"(mbar), "l"(pol) : "memory");
}
__device__ __forceinline__ void bulk_s2g(void* dst, uint32_t src_smem, uint32_t bytes,
                                         uint64_t pol) {
    asm volatile(
        "cp.async.bulk.global.shared::cta.bulk_group.L2::cache_hint [%0], [%1], %2, %3;"
        :: "l"(dst), "r"(src_smem), "r"(bytes), "l"(pol) : "memory");
}

__global__ __launch_bounds__(THREADS, 1)
void lif_tma_kernel(const char* __restrict__ gin, char* __restrict__ gout,
                    int n_chunks) {
    extern __shared__ char smem[];
    const uint32_t sbase = smem_u32(smem);
    const int tid = threadIdx.x;
    const int stride = gridDim.x;

    if ((int)blockIdx.x >= n_chunks) return;
    // Block-strided chunks: local l -> global chunk blockIdx.x + l*stride.
    const int ncl = (n_chunks - (int)blockIdx.x + stride - 1) / stride;

    const uint64_t pol = make_evict_first_policy();   // stream-once data

    if (tid == 0) {
        #pragma unroll
        for (int b = 0; b < NBUF; b++) mbar_init(sbase + 8 * b, 1);
        asm volatile("fence.proxy.async.shared::cta;" ::: "memory");
    }
    __syncthreads();

    // Prologue: prefetch up to 3 chunks.
    if (tid == 0) {
        int pre = ncl < 3 ? ncl : 3;
        for (int l = 0; l < pre; l++) {
            long long g = (long long)blockIdx.x + (long long)l * stride;
            mbar_expect(sbase + 8 * l, CHUNK_BYTES);
            bulk_g2s(sbase + SM_IN + l * CHUNK_BYTES,
                     gin + g * CHUNK_BYTES, CHUNK_BYTES, sbase + 8 * l, pol);
        }
    }

    for (int l = 0; l < ncl; l++) {
        const int b = l & (NBUF - 1);
        const long long g = (long long)blockIdx.x + (long long)l * stride;

        // Keep the load pipeline full BEFORE scanning: buffer (l+3)&3 held
        // chunk l-1, whose store was committed at the end of iter l-1;
        // wait_group.read 0 guarantees its smem has been fully read out.
        if (tid == 0 && l + 3 < ncl) {
            asm volatile("cp.async.bulk.wait_group.read 0;" ::: "memory");
            const int nb = (l + 3) & (NBUF - 1);
            const long long ng = (long long)blockIdx.x + (long long)(l + 3) * stride;
            mbar_expect(sbase + 8 * nb, CHUNK_BYTES);
            bulk_g2s(sbase + SM_IN + nb * CHUNK_BYTES,
                     gin + ng * CHUNK_BYTES, CHUNK_BYTES, sbase + 8 * nb, pol);
        }

        // Wait for load of chunk l (buffer b, 4-use parity).
        mbar_wait(sbase + 8 * b, (l >> 2) & 1);

        // Streaming in-place scan: read f4, compute, write spikes back.
        float4* row = (float4*)(smem + SM_IN + b * CHUNK_BYTES) + tid * LIF_TV;
        float mem = 0.0f;
        bool sp = false;
        #pragma unroll
        for (int k = 0; k < LIF_TV; k++) {
            float4 v = row[k];
            float4 o;
            float t;
            t = __fadd_rn(__fmul_rn(mem, LIF_DECAY), v.x);
            mem = sp ? v.x : t;  sp = mem > LIF_THRESH;  o.x = sp ? 1.0f : 0.0f;
            t = __fadd_rn(__fmul_rn(mem, LIF_DECAY), v.y);
            mem = sp ? v.y : t;  sp = mem > LIF_THRESH;  o.y = sp ? 1.0f : 0.0f;
            t = __fadd_rn(__fmul_rn(mem, LIF_DECAY), v.z);
            mem = sp ? v.z : t;  sp = mem > LIF_THRESH;  o.z = sp ? 1.0f : 0.0f;
            t = __fadd_rn(__fmul_rn(mem, LIF_DECAY), v.w);
            mem = sp ? v.w : t;  sp = mem > LIF_THRESH;  o.w = sp ? 1.0f : 0.0f;
            row[k] = o;
        }

        // Publish STS to the async proxy, then store chunk l.
        asm volatile("fence.proxy.async.shared::cta;" ::: "memory");
        __syncthreads();
        if (tid == 0) {
            bulk_s2g(gout + g * CHUNK_BYTES,
                     sbase + SM_IN + b * CHUNK_BYTES, CHUNK_BYTES, pol);
            asm volatile("cp.async.bulk.commit_group;" ::: "memory");
        }
    }

    // Keep smem alive until all pending bulk stores have read it.
    if (tid == 0)
        asm volatile("cp.async.bulk.wait_group.read 0;" ::: "memory");
}

// Scalar tail for rows not covered by full chunks.
__global__ void lif_scan_tail_kernel(const float* __restrict__ x,
                                     float* __restrict__ out,
                                     long long row_start, long long n_rows) {
    long long r = row_start + blockIdx.x * (long long)blockDim.x + threadIdx.x;
    if (r >= n_rows) return;
    const float* xr = x + r * LIF_T;
    float* orow = out + r * LIF_T;
    float mem = 0.0f;
    bool sp = false;
    #pragma unroll 4
    for (int t = 0; t < LIF_T; t++) {
        float tt = __fadd_rn(__fmul_rn(mem, LIF_DECAY), xr[t]);
        mem = sp ? xr[t] : tt;
        sp = mem > LIF_THRESH;
        orow[t] = sp ? 1.0f : 0.0f;
    }
}

extern "C" void kernel_launch(void* const* d_in, const int* in_sizes, int n_in,
                              void* d_out, int out_size) {
    const float* x = (const float*)d_in[0];
    float* out = (float*)d_out;

    long long total = (long long)in_sizes[0];
    long long n_rows = total / LIF_T;                 // 524288
    long long n_chunks = n_rows / CHUNK_ROWS;         // 4096

    if (n_chunks > 0) {
        static int smem_set = 0;
        if (!smem_set) {
            cudaFuncSetAttribute(lif_tma_kernel,
                                 cudaFuncAttributeMaxDynamicSharedMemorySize, SM_TOTAL);
            smem_set = 1;
        }
        // Proven best: 128 CTAs, perfectly balanced (4096/128 = 32 each).
        long long grid = 128;
        if (n_chunks < grid) grid = n_chunks;
        lif_tma_kernel<<<(unsigned)grid, THREADS, SM_TOTAL>>>(
            (const char*)x, (char*)out, (int)n_chunks);
    }

    long long done_rows = n_chunks * CHUNK_ROWS;
    long long rem = n_rows - done_rows;
    if (rem > 0) {
        int threads = 128;
        int blocks = (int)((rem + threads - 1) / threads);
        lif_scan_tail_kernel<<<blocks, threads>>>(x, out, done_rows, n_rows);
    }
}